// round 4
// baseline (speedup 1.0000x reference)
#include <cuda_runtime.h>

// Problem constants
#define S        1048576            // 1024*1024
#define S4       (S / 4)
#define TPB      256
#define NSLAB    10                 // TT0:r0, TT1:r0..2, TT2:r0..2, TT3:r0..2
#define BPS      96                 // blocks per slab (BPS*TPB divisible by 3!)
#define STRIDE   (BPS * TPB)        // 24576 float4s  (== 0 mod 3)
#define TSTRIDE  (STRIDE * 4 / 3)   // 32768 (z-index advance per iteration)
#define SLAB_F4  (3 * (S / 4))      // 786432 float4s per slab
#define NIT      (SLAB_F4 / STRIDE) // 32 iterations per thread
#define NCOMP    30                 // 10 slabs x 3 q-components

// Deterministic scratch (no device allocation allowed)
__device__ float        g_bpart[NCOMP * BPS];   // [comp][BPS]
__device__ float        g_f[3];
__device__ unsigned int g_ctr = 0;              // reset by last block each call

// ---------------------------------------------------------------------------
// Kernel A (fused reduce + finalize):
//   slab = bid % NSLAB  (same-s-range blocks co-scheduled -> z dedups in L1/L2)
// Each thread streams COALESCED float4s of its slab. For float4 index c4:
//   elements e = 4*c4+i ;  s = t + (p+i)/3 ;  q = (p+i) mod 3 ;  p = c4 mod 3
// p is loop-invariant (STRIDE % 3 == 0). Accumulate branchlessly into b_k
// (k = i mod 3, compile-time), weights w_i in {z[t], z[t+1]} via 2 selects,
// un-rotate b -> a once at the end.
// ---------------------------------------------------------------------------
__global__ void __launch_bounds__(TPB)
reduce_k(const float* __restrict__ z,
         const float* __restrict__ t0,
         const float* __restrict__ t1,
         const float* __restrict__ t2,
         const float* __restrict__ t3) {
    const int slab = blockIdx.x % NSLAB;
    const int blk  = blockIdx.x / NSLAB;

    const float* tsel = (slab == 0) ? t0 : (slab <= 3 ? t1 : (slab <= 6 ? t2 : t3));
    const int    r    = (slab == 0) ? 0 : (slab - 1) % 3;
    const float4* bp  = reinterpret_cast<const float4*>(tsel + (size_t)r * 3u * S);

    int c4 = blk * TPB + threadIdx.x;      // coalesced float4 stream
    int t  = (c4 * 4) / 3;                 // z index of first element
    const int  p  = c4 % 3;                // loop-invariant phase
    const bool p0 = (p == 0), p2 = (p == 2);

    float b0 = 0.0f, b1 = 0.0f, b2 = 0.0f;

#pragma unroll 4
    for (int it = 0; it < NIT; it++) {
        float4 v  = __ldg(bp + c4);
        float  za = __ldg(z + t);
        float  zb = __ldg(z + t + 1);
        float  w1 = p2 ? zb : za;          // weight for element i=1
        float  w2 = p0 ? za : zb;          // weight for element i=2
        b0 += za * v.x;                    // i=0 (w0 = za always)
        b1 += w1 * v.y;                    // i=1
        b2 += w2 * v.z;                    // i=2
        b0 += zb * v.w;                    // i=3 (w3 = zb always)
        c4 += STRIDE;
        t  += TSTRIDE;
    }

    // Un-rotate: a_q = b_{(q-p) mod 3}
    float a0 = p0 ? b0 : (p2 ? b1 : b2);
    float a1 = p0 ? b1 : (p2 ? b2 : b0);
    float a2 = p0 ? b2 : (p2 ? b0 : b1);

    // Warp reduction of 3 components
    const unsigned FULL = 0xffffffffu;
#pragma unroll
    for (int off = 16; off >= 1; off >>= 1) {
        a0 += __shfl_down_sync(FULL, a0, off);
        a1 += __shfl_down_sync(FULL, a1, off);
        a2 += __shfl_down_sync(FULL, a2, off);
    }

    __shared__ float sred[TPB / 32][3];
    const int warp = threadIdx.x >> 5;
    const int lane = threadIdx.x & 31;
    if (lane == 0) { sred[warp][0] = a0; sred[warp][1] = a1; sred[warp][2] = a2; }
    __syncthreads();

    if (threadIdx.x < 3) {
        float s = 0.0f;
#pragma unroll
        for (int w = 0; w < TPB / 32; w++) s += sred[w][threadIdx.x];
        g_bpart[(slab * 3 + threadIdx.x) * BPS + blk] = s;   // deterministic
    }

    // ---- fused finalize: last block computes f = V0 @ V1 @ V2 @ V3 ----
    __shared__ bool amLast;
    __threadfence();
    if (threadIdx.x == 0)
        amLast = (atomicAdd(&g_ctr, 1u) == (unsigned)(gridDim.x - 1));
    __syncthreads();

    if (amLast) {
        __threadfence();                   // acquire: see all blocks' partials
        __shared__ float sV[NCOMP][8];
        const int comp = threadIdx.x >> 3;     // 0..31 (use 0..29)
        const int part = threadIdx.x & 7;
        if (comp < NCOMP) {
            const float4* pp = reinterpret_cast<const float4*>(g_bpart + comp * BPS) + part * 3;
            float s = 0.0f;
#pragma unroll
            for (int j = 0; j < 3; j++) { float4 v = pp[j]; s += v.x + v.y + v.z + v.w; }
            sV[comp][part] = s;
        }
        __syncthreads();

        if (threadIdx.x == 0) {
            float V[NCOMP];
#pragma unroll
            for (int i = 0; i < NCOMP; i++) {
                float s = 0.0f;
#pragma unroll
                for (int j = 0; j < 8; j++) s += sV[i][j];
                V[i] = s;
            }
            float f0 = V[0], f1 = V[1], f2 = V[2];        // V0 : (1,3)
#pragma unroll
            for (int c = 0; c < 3; c++) {                 // V1,V2,V3 (3x3 [r*3+q])
                const float* M = V + 3 + c * 9;
                float g0 = f0 * M[0] + f1 * M[3] + f2 * M[6];
                float g1 = f0 * M[1] + f1 * M[4] + f2 * M[7];
                float g2 = f0 * M[2] + f1 * M[5] + f2 * M[8];
                f0 = g0; f1 = g1; f2 = g2;
            }
            g_f[0] = f0; g_f[1] = f1; g_f[2] = f2;
            g_ctr = 0;                     // reset for next graph replay
        }
    }
}

// ---------------------------------------------------------------------------
// Kernel C: out[s] = f0*TT4[0,s,0] + f1*TT4[1,s,0] + f2*TT4[2,s,0]
// ---------------------------------------------------------------------------
__global__ void __launch_bounds__(TPB)
bcast_k(const float* __restrict__ t4, float* __restrict__ out) {
    const int idx = blockIdx.x * TPB + threadIdx.x;   // 0 .. S4-1
    const float f0 = g_f[0];
    const float f1 = g_f[1];
    const float f2 = g_f[2];

    const float4* p = reinterpret_cast<const float4*>(t4);
    float4 a = p[idx];
    float4 b = p[S4 + idx];
    float4 c = p[2 * S4 + idx];

    float4 o;
    o.x = f0 * a.x + f1 * b.x + f2 * c.x;
    o.y = f0 * a.y + f1 * b.y + f2 * c.y;
    o.z = f0 * a.z + f1 * b.z + f2 * c.z;
    o.w = f0 * a.w + f1 * b.w + f2 * c.w;
    reinterpret_cast<float4*>(out)[idx] = o;
}

// ---------------------------------------------------------------------------
extern "C" void kernel_launch(void* const* d_in, const int* in_sizes, int n_in,
                              void* d_out, int out_size) {
    const float* z  = (const float*)d_in[0];
    const float* t0 = (const float*)d_in[1];
    const float* t1 = (const float*)d_in[2];
    const float* t2 = (const float*)d_in[3];
    const float* t3 = (const float*)d_in[4];
    const float* t4 = (const float*)d_in[5];
    float* out = (float*)d_out;

    reduce_k<<<NSLAB * BPS, TPB>>>(z, t0, t1, t2, t3);
    bcast_k<<<S4 / TPB, TPB>>>(t4, out);
}

// round 5
// speedup vs baseline: 1.1842x; 1.1842x over previous
#include <cuda_runtime.h>

// Problem constants
#define S      1048576        // 1024*1024
#define S4     (S / 4)        // float4 chunks per slab (262144)
#define TPB    256
#define NSLAB  10             // TT0:r0, TT1:r0..2, TT2:r0..2, TT3:r0..2
#define PBLK   128            // reduce blocks per slab
#define NITER  (S4 / (PBLK * TPB))   // 8 grid-stride iterations per thread
#define NCOMP  30             // 10 slabs x 3 q-components
#define RBLK   (NSLAB * PBLK) // 1280 reduce blocks
#define CBLK   512            // bcast blocks (each thread: 2 chunks)
// Deadlock safety: __launch_bounds__(TPB,4) -> >=4 CTAs/SM -> >=592 resident
// slots > CBLK=512 spinners, so reduce blocks always progress.

// Deterministic scratch (no device allocation allowed)
__device__ float        g_bpart[NCOMP * PBLK];   // [comp][PBLK]
__device__ float        g_f[3];
__device__ unsigned int g_ctr  = 0;              // reduce-completion counter
__device__ volatile int g_flag = 0;              // f-ready flag
__device__ unsigned int g_done = 0;              // bcast-completion counter

__global__ void __launch_bounds__(TPB, 4)
mega_k(const float* __restrict__ z,
       const float* __restrict__ t0,
       const float* __restrict__ t1,
       const float* __restrict__ t2,
       const float* __restrict__ t3,
       const float* __restrict__ t4,
       float* __restrict__ out) {
    if (blockIdx.x < RBLK) {
        // ================= reduce path (identical to R3 body) =============
        const int slab = blockIdx.x % NSLAB;   // co-schedule same s-range
        const int blk  = blockIdx.x / NSLAB;

        const float* base;
        {
            const int r = (slab == 0) ? 0 : ((slab - 1) % 3);
            const float* t = (slab == 0) ? t0 : (slab <= 3 ? t1 : (slab <= 6 ? t2 : t3));
            base = t + (size_t)r * (3u * S);
        }
        const float4* bp = reinterpret_cast<const float4*>(base);
        const float4* zp = reinterpret_cast<const float4*>(z);

        float a0 = 0.0f, a1 = 0.0f, a2 = 0.0f;

        int c = blk * TPB + threadIdx.x;           // chunk idx, stride PBLK*TPB
#pragma unroll
        for (int it = 0; it < NITER; it++, c += PBLK * TPB) {
            float4 zv = zp[c];
            const float4* p = bp + (size_t)c * 3;
            float4 v0 = p[0];
            float4 v1 = p[1];
            float4 v2 = p[2];
            // 12 consecutive floats = 4 s x 3 q ; elem e -> (s=e/3, q=e%3)
            a0 += zv.x * v0.x;  a1 += zv.x * v0.y;  a2 += zv.x * v0.z;
            a0 += zv.y * v0.w;  a1 += zv.y * v1.x;  a2 += zv.y * v1.y;
            a0 += zv.z * v1.z;  a1 += zv.z * v1.w;  a2 += zv.z * v2.x;
            a0 += zv.w * v2.y;  a1 += zv.w * v2.z;  a2 += zv.w * v2.w;
        }

        const unsigned FULL = 0xffffffffu;
#pragma unroll
        for (int off = 16; off >= 1; off >>= 1) {
            a0 += __shfl_down_sync(FULL, a0, off);
            a1 += __shfl_down_sync(FULL, a1, off);
            a2 += __shfl_down_sync(FULL, a2, off);
        }

        __shared__ float sred[TPB / 32][3];
        const int warp = threadIdx.x >> 5;
        const int lane = threadIdx.x & 31;
        if (lane == 0) { sred[warp][0] = a0; sred[warp][1] = a1; sred[warp][2] = a2; }
        __syncthreads();

        if (threadIdx.x < 3) {
            float s = 0.0f;
#pragma unroll
            for (int w = 0; w < TPB / 32; w++) s += sred[w][threadIdx.x];
            g_bpart[(slab * 3 + threadIdx.x) * PBLK + blk] = s;   // deterministic
        }

        // ---- last reduce block: finalize f = V0 @ V1 @ V2 @ V3, raise flag
        __shared__ bool amLast;
        __threadfence();
        if (threadIdx.x == 0)
            amLast = (atomicAdd(&g_ctr, 1u) == (unsigned)(RBLK - 1));
        __syncthreads();

        if (amLast) {
            __threadfence();                       // see all blocks' partials
            __shared__ float sV[NCOMP][8];
            const int comp = threadIdx.x >> 3;     // 0..31 (use 0..29)
            const int part = threadIdx.x & 7;      // 8 parts x 16 partials
            if (comp < NCOMP) {
                const float4* pp =
                    reinterpret_cast<const float4*>(g_bpart + comp * PBLK) + part * 4;
                float s = 0.0f;
#pragma unroll
                for (int j = 0; j < 4; j++) { float4 v = pp[j]; s += v.x + v.y + v.z + v.w; }
                sV[comp][part] = s;
            }
            __syncthreads();

            if (threadIdx.x == 0) {
                float V[NCOMP];
#pragma unroll
                for (int i = 0; i < NCOMP; i++) {
                    float s = 0.0f;
#pragma unroll
                    for (int j = 0; j < 8; j++) s += sV[i][j];
                    V[i] = s;
                }
                float f0 = V[0], f1 = V[1], f2 = V[2];       // V0 : (1,3)
#pragma unroll
                for (int cc = 0; cc < 3; cc++) {             // V1,V2,V3 (3x3 [r*3+q])
                    const float* M = V + 3 + cc * 9;
                    float g0 = f0 * M[0] + f1 * M[3] + f2 * M[6];
                    float g1 = f0 * M[1] + f1 * M[4] + f2 * M[7];
                    float g2 = f0 * M[2] + f1 * M[5] + f2 * M[8];
                    f0 = g0; f1 = g1; f2 = g2;
                }
                g_f[0] = f0; g_f[1] = f1; g_f[2] = f2;
                g_ctr = 0;                          // reset for next replay
                __threadfence();                    // publish g_f before flag
                g_flag = 1;                         // release
            }
        }
    } else {
        // ================= bcast path: prefetch -> spin -> FMA+store ======
        const int cid = blockIdx.x - RBLK;
        const int i0  = cid * (2 * TPB) + threadIdx.x;   // chunk 0 (coalesced)
        const int i1  = i0 + TPB;                        // chunk 1 (coalesced)

        const float4* p = reinterpret_cast<const float4*>(t4);
        // Prefetch TT4 data NOW so its DRAM traffic overlaps the reduce phase.
        float4 a0v = p[i0];
        float4 b0v = p[S4 + i0];
        float4 c0v = p[2 * S4 + i0];
        float4 a1v = p[i1];
        float4 b1v = p[S4 + i1];
        float4 c1v = p[2 * S4 + i1];
        asm volatile("" ::: "memory");   // keep loads issued before the spin

        __shared__ float sf[3];
        if (threadIdx.x == 0) {
            while (g_flag == 0) __nanosleep(64);
            __threadfence();             // acquire: order g_f reads after flag
            sf[0] = g_f[0]; sf[1] = g_f[1]; sf[2] = g_f[2];
        }
        __syncthreads();
        const float f0 = sf[0], f1 = sf[1], f2 = sf[2];

        float4 o;
        o.x = f0 * a0v.x + f1 * b0v.x + f2 * c0v.x;
        o.y = f0 * a0v.y + f1 * b0v.y + f2 * c0v.y;
        o.z = f0 * a0v.z + f1 * b0v.z + f2 * c0v.z;
        o.w = f0 * a0v.w + f1 * b0v.w + f2 * c0v.w;
        reinterpret_cast<float4*>(out)[i0] = o;
        o.x = f0 * a1v.x + f1 * b1v.x + f2 * c1v.x;
        o.y = f0 * a1v.y + f1 * b1v.y + f2 * c1v.y;
        o.z = f0 * a1v.z + f1 * b1v.z + f2 * c1v.z;
        o.w = f0 * a1v.w + f1 * b1v.w + f2 * c1v.w;
        reinterpret_cast<float4*>(out)[i1] = o;

        __syncthreads();
        if (threadIdx.x == 0) {
            __threadfence();
            if (atomicAdd(&g_done, 1u) == (unsigned)(CBLK - 1)) {
                g_done = 0;              // reset handshake for next replay
                g_flag = 0;
            }
        }
    }
}

// ---------------------------------------------------------------------------
extern "C" void kernel_launch(void* const* d_in, const int* in_sizes, int n_in,
                              void* d_out, int out_size) {
    const float* z  = (const float*)d_in[0];
    const float* t0 = (const float*)d_in[1];
    const float* t1 = (const float*)d_in[2];
    const float* t2 = (const float*)d_in[3];
    const float* t3 = (const float*)d_in[4];
    const float* t4 = (const float*)d_in[5];
    float* out = (float*)d_out;

    mega_k<<<RBLK + CBLK, TPB>>>(z, t0, t1, t2, t3, t4, out);
}